// round 3
// baseline (speedup 1.0000x reference)
#include <cuda_runtime.h>
#include <cstdint>

#define QMAX 1024
#define NMAX 50048
#define BM 128
#define BN 128
#define BK 16

// Static device scratch (allocation-free per harness rules)
__device__ float g_d2[NMAX];
__device__ float g_S[(size_t)QMAX * 50000];
__device__ int   g_lab32;   // 1 if targets buffer is int32, 0 if int64

// ---------------------------------------------------------------------------
// Kernel 1: squared norms of data rows. One warp per row.
// Thread (0,0) also sniffs the targets dtype: if the buffer is really int64,
// all high 32-bit words are zero; if int32, odd words are labels (rarely all 0).
// ---------------------------------------------------------------------------
__global__ void d2_kernel(const float* __restrict__ data,
                          const unsigned int* __restrict__ targets_w,
                          int N, int D) {
    if (blockIdx.x == 0 && threadIdx.x == 0) {
        int is32 = 0;
        #pragma unroll 1
        for (int w = 1; w < 128; w += 2)
            if (targets_w[w] != 0u) { is32 = 1; break; }
        g_lab32 = is32;
    }
    int row = blockIdx.x * 8 + (threadIdx.x >> 5);
    if (row >= N) return;
    int lane = threadIdx.x & 31;
    const float4* p = (const float4*)(data + (size_t)row * D);
    float s = 0.f;
    int d4 = D >> 2;
    for (int i = lane; i < d4; i += 32) {
        float4 v = p[i];
        s += v.x * v.x + v.y * v.y + v.z * v.z + v.w * v.w;
    }
    #pragma unroll
    for (int o = 16; o; o >>= 1) s += __shfl_xor_sync(0xffffffffu, s, o);
    if (lane == 0) g_d2[row] = s;
}

// ---------------------------------------------------------------------------
// Packed f32x2 FMA helpers (sm_100+): 2 FMAs per issue on the fma pipe.
// ---------------------------------------------------------------------------
__device__ __forceinline__ unsigned long long ffma2(unsigned long long a,
                                                    unsigned long long b,
                                                    unsigned long long c) {
    unsigned long long d;
    asm("fma.rn.f32x2 %0, %1, %2, %3;" : "=l"(d) : "l"(a), "l"(b), "l"(c));
    return d;
}
__device__ __forceinline__ unsigned long long dup2(float x) {
    unsigned long long d;
    unsigned int u = __float_as_uint(x);
    asm("mov.b64 %0, {%1, %1};" : "=l"(d) : "r"(u));
    return d;
}

// ---------------------------------------------------------------------------
// Kernel 2: S[q][n] = ||d_n||^2 - 2 * <X_q, d_n>   (monotone in distance;
// ||x_q||^2 is constant per query so irrelevant for ranking).
// Classic smem-tiled GEMM: BM=128, BN=128, BK=16, 256 threads, 8x8/thread
// computed as 8x4 f32x2 pairs.
// ---------------------------------------------------------------------------
__global__ __launch_bounds__(256, 2)
void gemm_dist_kernel(const float* __restrict__ X, const float* __restrict__ data,
                      int Q, int N, int D) {
    __shared__ float As[BK][BM + 4];
    __shared__ float Bs[BK][BN + 4];
    __shared__ float Ds[BN];   // staged d2 for this column tile

    int bm = blockIdx.y * BM;
    int bn = blockIdx.x * BN;
    int tid = threadIdx.x;
    int tx = tid & 15;   // 0..15  -> n sub-tile
    int ty = tid >> 4;   // 0..15  -> q sub-tile

    // Stage d2 for the 128 columns this CTA owns (coalesced, once).
    if (tid < BN) {
        int n = bn + tid;
        Ds[tid] = (n < N) ? g_d2[n] : 0.f;
    }

    unsigned long long acc[8][4];
    #pragma unroll
    for (int i = 0; i < 8; i++)
        #pragma unroll
        for (int j = 0; j < 4; j++) acc[i][j] = 0ull;  // bits(0,0) == (0.f,0.f)

    int lr = tid >> 2;         // 0..63 : tile row
    int lc = (tid & 3) * 4;    // 0,4,8,12 : k offset (float4)

    for (int k0 = 0; k0 < D; k0 += BK) {
        #pragma unroll
        for (int h = 0; h < 2; h++) {
            int r = lr + h * 64;
            // A tile (queries)
            float4 a = make_float4(0.f, 0.f, 0.f, 0.f);
            if (bm + r < Q)
                a = *(const float4*)(X + (size_t)(bm + r) * D + k0 + lc);
            As[lc + 0][r] = a.x; As[lc + 1][r] = a.y;
            As[lc + 2][r] = a.z; As[lc + 3][r] = a.w;
            // B tile (data points)
            float4 b = make_float4(0.f, 0.f, 0.f, 0.f);
            if (bn + r < N)
                b = *(const float4*)(data + (size_t)(bn + r) * D + k0 + lc);
            Bs[lc + 0][r] = b.x; Bs[lc + 1][r] = b.y;
            Bs[lc + 2][r] = b.z; Bs[lc + 3][r] = b.w;
        }
        __syncthreads();

        #pragma unroll
        for (int k = 0; k < BK; k++) {
            unsigned long long bp[4], ad[8];
            #pragma unroll
            for (int j = 0; j < 4; j++)
                bp[j] = *(const unsigned long long*)&Bs[k][tx * 8 + j * 2];
            #pragma unroll
            for (int i = 0; i < 8; i++)
                ad[i] = dup2(As[k][ty * 8 + i]);
            #pragma unroll
            for (int i = 0; i < 8; i++)
                #pragma unroll
                for (int j = 0; j < 4; j++)
                    acc[i][j] = ffma2(ad[i], bp[j], acc[i][j]);
        }
        __syncthreads();
    }

    // Epilogue: S = d2 - 2*dot
    #pragma unroll
    for (int i = 0; i < 8; i++) {
        int q = bm + ty * 8 + i;
        if (q >= Q) continue;
        float* Srow = g_S + (size_t)q * N;
        #pragma unroll
        for (int j = 0; j < 4; j++) {
            int c = tx * 8 + j * 2;
            int n = bn + c;
            unsigned long long v = acc[i][j];
            float lo = __uint_as_float((unsigned int)v);
            float hi = __uint_as_float((unsigned int)(v >> 32));
            if (n < N)     Srow[n]     = Ds[c]     - 2.f * lo;
            if (n + 1 < N) Srow[n + 1] = Ds[c + 1] - 2.f * hi;
        }
    }
}

// ---------------------------------------------------------------------------
// Kernel 3: per-query top-10 (ascending sq distance, ties -> lower index,
// matching jax.lax.top_k stability) then mode of neighbor labels
// (ties -> smallest class, matching argmax over one-hot counts).
// One CTA (256 threads) per query.
// ---------------------------------------------------------------------------
__device__ __forceinline__ int load_label(const void* targets, int idx, int lab32) {
    if (lab32) return ((const int*)targets)[idx];
    return (int)((const long long*)targets)[idx];
}

__global__ void topk_mode_kernel(const void* __restrict__ targets,
                                 float* __restrict__ out, int N) {
    const int q = blockIdx.x;
    const float* row = g_S + (size_t)q * N;
    const int t = threadIdx.x;
    const float INF = __int_as_float(0x7f800000);

    float bv[10]; int bi[10];
    #pragma unroll
    for (int r = 0; r < 10; r++) { bv[r] = INF; bi[r] = 0x7fffffff; }
    float worst = INF;

    for (int n = t; n < N; n += 256) {
        float v = row[n];
        if (v < worst) {
            int p = 9;
            while (p > 0 && v < bv[p - 1]) {
                bv[p] = bv[p - 1]; bi[p] = bi[p - 1]; p--;
            }
            bv[p] = v; bi[p] = n;
            worst = bv[9];
        }
    }

    __shared__ float sv[2560];
    __shared__ int   si[2560];
    __shared__ float rv[256];
    __shared__ int   ri[256];
    __shared__ int   rslot[256];

    #pragma unroll
    for (int r = 0; r < 10; r++) { sv[t * 10 + r] = bv[r]; si[t * 10 + r] = bi[r]; }
    __syncthreads();

    __shared__ int s_topidx[10];
    for (int round = 0; round < 10; round++) {
        float mv = INF; int mi = 0x7fffffff; int ms = t * 10;
        #pragma unroll
        for (int r = 0; r < 10; r++) {
            float v = sv[t * 10 + r]; int i = si[t * 10 + r];
            if (v < mv || (v == mv && i < mi)) { mv = v; mi = i; ms = t * 10 + r; }
        }
        rv[t] = mv; ri[t] = mi; rslot[t] = ms;
        __syncthreads();
        if (t == 0) {
            float gv = INF; int gi = 0x7fffffff; int gs = 0;
            for (int u = 0; u < 256; u++) {
                if (rv[u] < gv || (rv[u] == gv && ri[u] < gi)) {
                    gv = rv[u]; gi = ri[u]; gs = rslot[u];
                }
            }
            s_topidx[round] = gi;
            sv[gs] = INF; si[gs] = 0x7fffffff;
        }
        __syncthreads();
    }

    if (t == 0) {
        int lab32 = g_lab32;
        int lab[10];
        for (int r = 0; r < 10; r++) lab[r] = load_label(targets, s_topidx[r], lab32);
        int bestc = -1, bestl = 0x7fffffff;
        for (int r = 0; r < 10; r++) {
            int c = 0;
            for (int s = 0; s < 10; s++) c += (lab[s] == lab[r]);
            int l = lab[r];
            if (c > bestc || (c == bestc && l < bestl)) { bestc = c; bestl = l; }
        }
        out[q] = (float)bestl;
    }
}

// ---------------------------------------------------------------------------
extern "C" void kernel_launch(void* const* d_in, const int* in_sizes, int n_in,
                              void* d_out, int out_size) {
    const float* X    = (const float*)d_in[0];
    const float* data = (const float*)d_in[1];
    const void*  targets = d_in[2];
    float*       out  = (float*)d_out;

    int szX = in_sizes[0], szD = in_sizes[1];
    // Defensive: X is the smaller matrix (queries), data the larger.
    if (szX > szD) {
        const float* tmp = X; X = data; data = tmp;
        int ts = szX; szX = szD; szD = ts;
    }
    int N = in_sizes[2];     // 50000 (targets element count)
    int D = szD / N;         // 512
    int Q = szX / D;         // 1024

    d2_kernel<<<(N + 7) / 8, 256>>>(data, (const unsigned int*)targets, N, D);

    dim3 g((N + BN - 1) / BN, (Q + BM - 1) / BM);
    gemm_dist_kernel<<<g, 256>>>(X, data, Q, N, D);

    topk_mode_kernel<<<Q, 256>>>(targets, out, N);
}

// round 8
// speedup vs baseline: 1.6010x; 1.6010x over previous
#include <cuda_runtime.h>
#include <cuda_bf16.h>
#include <cstdint>

#define QMAX 1024
#define NMAX 50048
#define KDIM 512
#define KC   32          // K per SMEM chunk
#define TILE 128         // CTA M and N tile
#define PITCH 40         // bf16 elements per SMEM row (80B: 16B-aligned, conflict-free)

// ---------------- static device scratch (256B aligned) ----------------
__device__ __align__(256) float         g_d2[NMAX];
__device__ __align__(256) float         g_S[(size_t)QMAX * 50000];
__device__ int           g_lab32;
__device__ __align__(256) __nv_bfloat16 g_Xhi[(size_t)QMAX * KDIM];
__device__ __align__(256) __nv_bfloat16 g_Xlo[(size_t)QMAX * KDIM];
__device__ __align__(256) __nv_bfloat16 g_Bhi[(size_t)NMAX * KDIM];
__device__ __align__(256) __nv_bfloat16 g_Blo[(size_t)NMAX * KDIM];

// ---------------- helpers ----------------
__device__ __forceinline__ uint32_t smem_u32(const void* p) {
    uint32_t a;
    asm("{ .reg .u64 t; cvta.to.shared.u64 t, %1; cvt.u32.u64 %0, t; }" : "=r"(a) : "l"(p));
    return a;
}
__device__ __forceinline__ void cp16(uint32_t dst, const void* src) {
    asm volatile("cp.async.cg.shared.global [%0], [%1], 16;" :: "r"(dst), "l"(src));
}
__device__ __forceinline__ void cp_commit() {
    asm volatile("cp.async.commit_group;" ::: "memory");
}
__device__ __forceinline__ void cp_wait1() {
    asm volatile("cp.async.wait_group 1;" ::: "memory");
}
__device__ __forceinline__ void cp_wait0() {
    asm volatile("cp.async.wait_group 0;" ::: "memory");
}
__device__ __forceinline__ void sts_zero16(uint32_t dst) {
    asm volatile("st.shared.v4.b32 [%0], {%1,%1,%1,%1};" :: "r"(dst), "r"(0) : "memory");
}
__device__ __forceinline__ void mma_bf16(float& c0, float& c1, float& c2, float& c3,
                                         uint32_t a0, uint32_t a1, uint32_t a2, uint32_t a3,
                                         uint32_t b0, uint32_t b1) {
    asm volatile(
        "mma.sync.aligned.m16n8k16.row.col.f32.bf16.bf16.f32 "
        "{%0,%1,%2,%3}, {%4,%5,%6,%7}, {%8,%9}, {%0,%1,%2,%3};"
        : "+f"(c0), "+f"(c1), "+f"(c2), "+f"(c3)
        : "r"(a0), "r"(a1), "r"(a2), "r"(a3), "r"(b0), "r"(b1));
}
__device__ __forceinline__ uint32_t lds32(const __nv_bfloat16* base, int elem) {
    return *(const uint32_t*)(base + elem);
}

// ---------------------------------------------------------------------------
// Kernel 1: fp32 -> (hi,lo) bf16 split; d2; label dtype sniff.
// ---------------------------------------------------------------------------
__global__ void conv_kernel(const float* __restrict__ data, const float* __restrict__ X,
                            const unsigned int* __restrict__ targets_w, int N, int Q) {
    if (blockIdx.x == 0 && threadIdx.x == 0) {
        int is32 = 0;
        #pragma unroll 1
        for (int w = 1; w < 128; w += 2)
            if (targets_w[w] != 0u) { is32 = 1; break; }
        g_lab32 = is32;
    }
    int row = blockIdx.x * 8 + (threadIdx.x >> 5);
    if (row >= N + Q) return;
    int lane = threadIdx.x & 31;

    if (row < N) {
        const float* src = data + (size_t)row * KDIM;
        __nv_bfloat16* hi = g_Bhi + (size_t)row * KDIM;
        __nv_bfloat16* lo = g_Blo + (size_t)row * KDIM;
        float s = 0.f;
        for (int k = lane; k < KDIM; k += 32) {
            float v = src[k];
            s += v * v;
            __nv_bfloat16 h = __float2bfloat16_rn(v);
            hi[k] = h;
            lo[k] = __float2bfloat16_rn(v - __bfloat162float(h));
        }
        #pragma unroll
        for (int o = 16; o; o >>= 1) s += __shfl_xor_sync(0xffffffffu, s, o);
        if (lane == 0) g_d2[row] = s;
    } else {
        int r = row - N;
        const float* src = X + (size_t)r * KDIM;
        __nv_bfloat16* hi = g_Xhi + (size_t)r * KDIM;
        __nv_bfloat16* lo = g_Xlo + (size_t)r * KDIM;
        for (int k = lane; k < KDIM; k += 32) {
            float v = src[k];
            __nv_bfloat16 h = __float2bfloat16_rn(v);
            hi[k] = h;
            lo[k] = __float2bfloat16_rn(v - __bfloat162float(h));
        }
    }
}

// ---------------------------------------------------------------------------
// Kernel 2: HMMA (mma.sync bf16) GEMM with 2-way split, fp32 accumulate.
// S[q][n] = d2[n] - 2*(Ahi*Bhi + Ahi*Blo + Alo*Bhi).
// CTA 128x128, 8 warps as 2(M) x 4(N), warp tile 64x32, KC=32 double-buffered.
// SMEM per buffer: 4 tiles (Ahi,Alo,Bhi,Blo) of 128 rows x PITCH(40) bf16.
// ---------------------------------------------------------------------------
#define TILE_BYTES (TILE * PITCH * 2)        // 10240
#define BUF_BYTES  (4 * TILE_BYTES)          // 40960

__global__ __launch_bounds__(256)
void gemm_mma_kernel(int Q, int N) {
    extern __shared__ char dynsmem[];
    uint32_t sb = smem_u32(dynsmem);
    float* Ds = (float*)dynsmem;                       // 128 floats (512B)
    const uint32_t SMEM_T0 = sb + 512;                 // buffer 0 base

    const int tid = threadIdx.x;
    const int wid = tid >> 5;
    const int lane = tid & 31;
    const int g  = lane >> 2;        // group id 0..7
    const int tg = lane & 3;         // thread in group
    const int wm = wid & 1;          // 0..1  (M)
    const int wn = wid >> 1;         // 0..3  (N)

    const int bm = blockIdx.x * TILE;
    const int bn = blockIdx.y * TILE;
    const int nrowsB = min(TILE, N - bn);

    if (tid < TILE) {
        int n = bn + tid;
        Ds[tid] = (n < N) ? g_d2[n] : 0.f;
    }

    const __nv_bfloat16* gAhi = g_Xhi + (size_t)bm * KDIM;
    const __nv_bfloat16* gAlo = g_Xlo + (size_t)bm * KDIM;
    const __nv_bfloat16* gBhi = g_Bhi + (size_t)bn * KDIM;
    const __nv_bfloat16* gBlo = g_Blo + (size_t)bn * KDIM;

    // accumulators: [mt][nt][4]
    float acc[4][4][4];
    #pragma unroll
    for (int i = 0; i < 4; i++)
        #pragma unroll
        for (int j = 0; j < 4; j++)
            #pragma unroll
            for (int e = 0; e < 4; e++) acc[i][j][e] = 0.f;

    // fill one buffer with chunk k0 (512 x 16B per tile, 2 per thread per tile)
    auto fill = [&](uint32_t buf, int k0) {
        #pragma unroll
        for (int i = 0; i < 2; i++) {
            int idx = i * 256 + tid;       // 0..511
            int r = idx >> 2;              // row 0..127
            int c = idx & 3;               // 16B unit (8 bf16)
            uint32_t dst = buf + (uint32_t)(r * (PITCH * 2) + c * 16);
            size_t go = (size_t)r * KDIM + k0 + c * 8;
            cp16(dst + 0 * TILE_BYTES, gAhi + go);            // A rows always valid (Q%128==0)
            cp16(dst + 1 * TILE_BYTES, gAlo + go);
            if (r < nrowsB) {
                cp16(dst + 2 * TILE_BYTES, gBhi + go);
                cp16(dst + 3 * TILE_BYTES, gBlo + go);
            } else {
                sts_zero16(dst + 2 * TILE_BYTES);
                sts_zero16(dst + 3 * TILE_BYTES);
            }
        }
    };

    const int NCH = KDIM / KC;   // 16
    fill(SMEM_T0, 0);
    cp_commit();

    for (int ch = 0; ch < NCH; ch++) {
        uint32_t buf = SMEM_T0 + (uint32_t)((ch & 1) * BUF_BYTES);
        if (ch + 1 < NCH) {
            fill(SMEM_T0 + (uint32_t)(((ch + 1) & 1) * BUF_BYTES), (ch + 1) * KC);
            cp_commit();
            cp_wait1();
        } else {
            cp_wait0();
        }
        __syncthreads();

        const __nv_bfloat16* sAhi = (const __nv_bfloat16*)(dynsmem + 512 + (ch & 1) * BUF_BYTES);
        const __nv_bfloat16* sAlo = sAhi + TILE * PITCH;
        const __nv_bfloat16* sBhi = sAlo + TILE * PITCH;
        const __nv_bfloat16* sBlo = sBhi + TILE * PITCH;

        #pragma unroll
        for (int ks = 0; ks < KC; ks += 16) {
            uint32_t aHi[4][4], aLo[4][4];
            #pragma unroll
            for (int mt = 0; mt < 4; mt++) {
                int m = wm * 64 + mt * 16 + g;
                int e0 = m * PITCH + ks + tg * 2;
                int e1 = (m + 8) * PITCH + ks + tg * 2;
                aHi[mt][0] = lds32(sAhi, e0);
                aHi[mt][1] = lds32(sAhi, e1);
                aHi[mt][2] = lds32(sAhi, e0 + 8);
                aHi[mt][3] = lds32(sAhi, e1 + 8);
                aLo[mt][0] = lds32(sAlo, e0);
                aLo[mt][1] = lds32(sAlo, e1);
                aLo[mt][2] = lds32(sAlo, e0 + 8);
                aLo[mt][3] = lds32(sAlo, e1 + 8);
            }
            #pragma unroll
            for (int nt = 0; nt < 4; nt++) {
                int n = wn * 32 + nt * 8 + g;
                int e = n * PITCH + ks + tg * 2;
                uint32_t bHi0 = lds32(sBhi, e), bHi1 = lds32(sBhi, e + 8);
                uint32_t bLo0 = lds32(sBlo, e), bLo1 = lds32(sBlo, e + 8);
                #pragma unroll
                for (int mt = 0; mt < 4; mt++) {
                    float* c = acc[mt][nt];
                    mma_bf16(c[0], c[1], c[2], c[3],
                             aHi[mt][0], aHi[mt][1], aHi[mt][2], aHi[mt][3], bHi0, bHi1);
                    mma_bf16(c[0], c[1], c[2], c[3],
                             aHi[mt][0], aHi[mt][1], aHi[mt][2], aHi[mt][3], bLo0, bLo1);
                    mma_bf16(c[0], c[1], c[2], c[3],
                             aLo[mt][0], aLo[mt][1], aLo[mt][2], aLo[mt][3], bHi0, bHi1);
                }
            }
        }
        __syncthreads();
    }

    // Epilogue: S = d2 - 2*dot, written as float2 per fragment row pair.
    #pragma unroll
    for (int mt = 0; mt < 4; mt++) {
        int q0 = bm + wm * 64 + mt * 16 + g;
        #pragma unroll
        for (int nt = 0; nt < 4; nt++) {
            int lc = wn * 32 + nt * 8 + tg * 2;   // local col
            int n = bn + lc;
            if (n < N) {
                float d0 = Ds[lc], d1 = Ds[lc + 1];
                float* c = acc[mt][nt];
                if (q0 < Q) {
                    float2 v = make_float2(d0 - 2.f * c[0], d1 - 2.f * c[1]);
                    *(float2*)(g_S + (size_t)q0 * N + n) = v;
                }
                if (q0 + 8 < Q) {
                    float2 v = make_float2(d0 - 2.f * c[2], d1 - 2.f * c[3]);
                    *(float2*)(g_S + (size_t)(q0 + 8) * N + n) = v;
                }
            }
        }
    }
}

// ---------------------------------------------------------------------------
// Kernel 3: per-query top-10 + mode (unchanged from passing version).
// ---------------------------------------------------------------------------
__device__ __forceinline__ int load_label(const void* targets, int idx, int lab32) {
    if (lab32) return ((const int*)targets)[idx];
    return (int)((const long long*)targets)[idx];
}

__global__ void topk_mode_kernel(const void* __restrict__ targets,
                                 float* __restrict__ out, int N) {
    const int q = blockIdx.x;
    const float* row = g_S + (size_t)q * N;
    const int t = threadIdx.x;
    const float INF = __int_as_float(0x7f800000);

    float bv[10]; int bi[10];
    #pragma unroll
    for (int r = 0; r < 10; r++) { bv[r] = INF; bi[r] = 0x7fffffff; }
    float worst = INF;

    for (int n = t; n < N; n += 256) {
        float v = row[n];
        if (v < worst) {
            int p = 9;
            while (p > 0 && v < bv[p - 1]) {
                bv[p] = bv[p - 1]; bi[p] = bi[p - 1]; p--;
            }
            bv[p] = v; bi[p] = n;
            worst = bv[9];
        }
    }

    __shared__ float sv[2560];
    __shared__ int   si[2560];
    __shared__ float rv[256];
    __shared__ int   ri[256];
    __shared__ int   rslot[256];

    #pragma unroll
    for (int r = 0; r < 10; r++) { sv[t * 10 + r] = bv[r]; si[t * 10 + r] = bi[r]; }
    __syncthreads();

    __shared__ int s_topidx[10];
    for (int round = 0; round < 10; round++) {
        float mv = INF; int mi = 0x7fffffff; int ms = t * 10;
        #pragma unroll
        for (int r = 0; r < 10; r++) {
            float v = sv[t * 10 + r]; int i = si[t * 10 + r];
            if (v < mv || (v == mv && i < mi)) { mv = v; mi = i; ms = t * 10 + r; }
        }
        rv[t] = mv; ri[t] = mi; rslot[t] = ms;
        __syncthreads();
        if (t == 0) {
            float gv = INF; int gi = 0x7fffffff; int gs = 0;
            for (int u = 0; u < 256; u++) {
                if (rv[u] < gv || (rv[u] == gv && ri[u] < gi)) {
                    gv = rv[u]; gi = ri[u]; gs = rslot[u];
                }
            }
            s_topidx[round] = gi;
            sv[gs] = INF; si[gs] = 0x7fffffff;
        }
        __syncthreads();
    }

    if (t == 0) {
        int lab32 = g_lab32;
        int lab[10];
        for (int r = 0; r < 10; r++) lab[r] = load_label(targets, s_topidx[r], lab32);
        int bestc = -1, bestl = 0x7fffffff;
        for (int r = 0; r < 10; r++) {
            int c = 0;
            for (int s = 0; s < 10; s++) c += (lab[s] == lab[r]);
            int l = lab[r];
            if (c > bestc || (c == bestc && l < bestl)) { bestc = c; bestl = l; }
        }
        out[q] = (float)bestl;
    }
}

// ---------------------------------------------------------------------------
extern "C" void kernel_launch(void* const* d_in, const int* in_sizes, int n_in,
                              void* d_out, int out_size) {
    const float* X    = (const float*)d_in[0];
    const float* data = (const float*)d_in[1];
    const void*  targets = d_in[2];
    float*       out  = (float*)d_out;

    int szX = in_sizes[0], szD = in_sizes[1];
    if (szX > szD) {
        const float* tmp = X; X = data; data = tmp;
        int ts = szX; szX = szD; szD = ts;
    }
    int N = in_sizes[2];     // 50000
    int Q = szX / KDIM;      // 1024

    const int smem_bytes = 512 + 2 * BUF_BYTES;   // 512 + 81920 = 82432
    cudaFuncSetAttribute(gemm_mma_kernel,
                         cudaFuncAttributeMaxDynamicSharedMemorySize, smem_bytes);

    conv_kernel<<<(N + Q + 7) / 8, 256>>>(data, X, (const unsigned int*)targets, N, Q);

    dim3 g((Q + TILE - 1) / TILE, (N + TILE - 1) / TILE);
    gemm_mma_kernel<<<g, 256, smem_bytes>>>(Q, N);

    topk_mode_kernel<<<Q, 256>>>(targets, out, N);
}

// round 12
// speedup vs baseline: 1.6956x; 1.0590x over previous
#include <cuda_runtime.h>
#include <cuda_bf16.h>
#include <cstdint>

#define QMAX 1024
#define NMAX 50048
#define KDIM 512
#define KC   32          // K per SMEM chunk
#define TILE 128         // CTA M and N tile
#define PITCH 40         // bf16 elements per SMEM row (80B: 16B-aligned, conflict-free)

// ---------------- static device scratch (256B aligned) ----------------
__device__ __align__(256) float         g_d2[NMAX];
__device__ __align__(256) float         g_S[(size_t)QMAX * 50000];
__device__ int           g_lab32;
__device__ __align__(256) __nv_bfloat16 g_Xhi[(size_t)QMAX * KDIM];
__device__ __align__(256) __nv_bfloat16 g_Xlo[(size_t)QMAX * KDIM];
__device__ __align__(256) __nv_bfloat16 g_Bhi[(size_t)NMAX * KDIM];
__device__ __align__(256) __nv_bfloat16 g_Blo[(size_t)NMAX * KDIM];

// ---------------- helpers ----------------
__device__ __forceinline__ uint32_t smem_u32(const void* p) {
    uint32_t a;
    asm("{ .reg .u64 t; cvta.to.shared.u64 t, %1; cvt.u32.u64 %0, t; }" : "=r"(a) : "l"(p));
    return a;
}
__device__ __forceinline__ void cp16(uint32_t dst, const void* src) {
    asm volatile("cp.async.cg.shared.global [%0], [%1], 16;" :: "r"(dst), "l"(src));
}
__device__ __forceinline__ void cp_commit() {
    asm volatile("cp.async.commit_group;" ::: "memory");
}
__device__ __forceinline__ void cp_wait1() {
    asm volatile("cp.async.wait_group 1;" ::: "memory");
}
__device__ __forceinline__ void cp_wait0() {
    asm volatile("cp.async.wait_group 0;" ::: "memory");
}
__device__ __forceinline__ void sts_zero16(uint32_t dst) {
    asm volatile("st.shared.v4.b32 [%0], {%1,%1,%1,%1};" :: "r"(dst), "r"(0) : "memory");
}
__device__ __forceinline__ void mma_bf16(float& c0, float& c1, float& c2, float& c3,
                                         uint32_t a0, uint32_t a1, uint32_t a2, uint32_t a3,
                                         uint32_t b0, uint32_t b1) {
    asm volatile(
        "mma.sync.aligned.m16n8k16.row.col.f32.bf16.bf16.f32 "
        "{%0,%1,%2,%3}, {%4,%5,%6,%7}, {%8,%9}, {%0,%1,%2,%3};"
        : "+f"(c0), "+f"(c1), "+f"(c2), "+f"(c3)
        : "r"(a0), "r"(a1), "r"(a2), "r"(a3), "r"(b0), "r"(b1));
}
__device__ __forceinline__ void ldsm4(uint32_t& r0, uint32_t& r1, uint32_t& r2, uint32_t& r3,
                                      uint32_t addr) {
    asm volatile("ldmatrix.sync.aligned.m8n8.x4.shared.b16 {%0,%1,%2,%3}, [%4];"
                 : "=r"(r0), "=r"(r1), "=r"(r2), "=r"(r3) : "r"(addr));
}
__device__ __forceinline__ void ldsm2(uint32_t& r0, uint32_t& r1, uint32_t addr) {
    asm volatile("ldmatrix.sync.aligned.m8n8.x2.shared.b16 {%0,%1}, [%2];"
                 : "=r"(r0), "=r"(r1) : "r"(addr));
}

// ---------------------------------------------------------------------------
// Kernel 1: fp32 -> (hi,lo) bf16 split; d2; label dtype sniff. float4 I/O.
// ---------------------------------------------------------------------------
__global__ void conv_kernel(const float* __restrict__ data, const float* __restrict__ X,
                            const unsigned int* __restrict__ targets_w, int N, int Q) {
    if (blockIdx.x == 0 && threadIdx.x == 0) {
        int is32 = 0;
        #pragma unroll 1
        for (int w = 1; w < 128; w += 2)
            if (targets_w[w] != 0u) { is32 = 1; break; }
        g_lab32 = is32;
    }
    int row = blockIdx.x * 8 + (threadIdx.x >> 5);
    if (row >= N + Q) return;
    int lane = threadIdx.x & 31;

    const float* src;
    __nv_bfloat16 *hi, *lo;
    bool isData = (row < N);
    if (isData) {
        src = data + (size_t)row * KDIM;
        hi = g_Bhi + (size_t)row * KDIM;
        lo = g_Blo + (size_t)row * KDIM;
    } else {
        int r = row - N;
        src = X + (size_t)r * KDIM;
        hi = g_Xhi + (size_t)r * KDIM;
        lo = g_Xlo + (size_t)r * KDIM;
    }

    float s = 0.f;
    #pragma unroll
    for (int it = 0; it < KDIM / 4 / 32; it++) {
        int k4 = it * 32 + lane;
        float4 v = ((const float4*)src)[k4];
        s += v.x * v.x + v.y * v.y + v.z * v.z + v.w * v.w;
        __nv_bfloat16 h0 = __float2bfloat16_rn(v.x);
        __nv_bfloat16 h1 = __float2bfloat16_rn(v.y);
        __nv_bfloat16 h2 = __float2bfloat16_rn(v.z);
        __nv_bfloat16 h3 = __float2bfloat16_rn(v.w);
        __nv_bfloat162 hp0; hp0.x = h0; hp0.y = h1;
        __nv_bfloat162 hp1; hp1.x = h2; hp1.y = h3;
        uint2 hw = make_uint2(*(uint32_t*)&hp0, *(uint32_t*)&hp1);
        ((uint2*)hi)[k4] = hw;
        __nv_bfloat162 lp0, lp1;
        lp0.x = __float2bfloat16_rn(v.x - __bfloat162float(h0));
        lp0.y = __float2bfloat16_rn(v.y - __bfloat162float(h1));
        lp1.x = __float2bfloat16_rn(v.z - __bfloat162float(h2));
        lp1.y = __float2bfloat16_rn(v.w - __bfloat162float(h3));
        uint2 lw = make_uint2(*(uint32_t*)&lp0, *(uint32_t*)&lp1);
        ((uint2*)lo)[k4] = lw;
    }
    if (isData) {
        #pragma unroll
        for (int o = 16; o; o >>= 1) s += __shfl_xor_sync(0xffffffffu, s, o);
        if (lane == 0) g_d2[row] = s;
    }
}

// ---------------------------------------------------------------------------
// Kernel 2: HMMA GEMM, bf16 2-way split, ldmatrix fragment loads.
// S[q][n] = d2[n] - 2*(Ahi*Bhi + Ahi*Blo + Alo*Bhi).
// CTA 128x128, 8 warps (2M x 4N), warp tile 64x32, KC=32 double-buffered.
// ---------------------------------------------------------------------------
#define TILE_BYTES (TILE * PITCH * 2)        // 10240
#define BUF_BYTES  (4 * TILE_BYTES)          // 40960

__global__ __launch_bounds__(256, 2)
void gemm_mma_kernel(int Q, int N) {
    extern __shared__ char dynsmem[];
    uint32_t sb = smem_u32(dynsmem);
    float* Ds = (float*)dynsmem;                       // 128 floats (512B)
    const uint32_t SMEM_T0 = sb + 512;                 // buffer 0 base

    const int tid = threadIdx.x;
    const int wid = tid >> 5;
    const int lane = tid & 31;
    const int g  = lane >> 2;
    const int tg = lane & 3;
    const int wm = wid & 1;          // 0..1  (M)
    const int wn = wid >> 1;         // 0..3  (N)

    const int bm = blockIdx.x * TILE;
    const int bn = blockIdx.y * TILE;
    const int nrowsB = min(TILE, N - bn);

    if (tid < TILE) {
        int n = bn + tid;
        Ds[tid] = (n < N) ? g_d2[n] : 0.f;
    }

    const __nv_bfloat16* gAhi = g_Xhi + (size_t)bm * KDIM;
    const __nv_bfloat16* gAlo = g_Xlo + (size_t)bm * KDIM;
    const __nv_bfloat16* gBhi = g_Bhi + (size_t)bn * KDIM;
    const __nv_bfloat16* gBlo = g_Blo + (size_t)bn * KDIM;

    // ldmatrix per-lane element offsets (in bf16 elements, before *2 bytes)
    // A (x4): row = wm*64 + mt*16 + (lane&15), colbase = (lane>>4)*8
    // B (x2): row = wn*32 + nt*8 + (lane&7),  colbase = ((lane>>3)&1)*8
    int aOff[4], bOff[4];
    #pragma unroll
    for (int mt = 0; mt < 4; mt++)
        aOff[mt] = (wm * 64 + mt * 16 + (lane & 15)) * PITCH + (lane >> 4) * 8;
    #pragma unroll
    for (int nt = 0; nt < 4; nt++)
        bOff[nt] = (wn * 32 + nt * 8 + (lane & 7)) * PITCH + ((lane >> 3) & 1) * 8;

    float acc[4][4][4];
    #pragma unroll
    for (int i = 0; i < 4; i++)
        #pragma unroll
        for (int j = 0; j < 4; j++)
            #pragma unroll
            for (int e = 0; e < 4; e++) acc[i][j][e] = 0.f;

    auto fill = [&](uint32_t buf, int k0) {
        #pragma unroll
        for (int i = 0; i < 2; i++) {
            int idx = i * 256 + tid;       // 0..511
            int r = idx >> 2;              // row 0..127
            int c = idx & 3;               // 16B unit (8 bf16)
            uint32_t dst = buf + (uint32_t)(r * (PITCH * 2) + c * 16);
            size_t go = (size_t)r * KDIM + k0 + c * 8;
            cp16(dst + 0 * TILE_BYTES, gAhi + go);   // A rows always valid (Q%128==0)
            cp16(dst + 1 * TILE_BYTES, gAlo + go);
            if (r < nrowsB) {
                cp16(dst + 2 * TILE_BYTES, gBhi + go);
                cp16(dst + 3 * TILE_BYTES, gBlo + go);
            } else {
                sts_zero16(dst + 2 * TILE_BYTES);
                sts_zero16(dst + 3 * TILE_BYTES);
            }
        }
    };

    const int NCH = KDIM / KC;   // 16
    fill(SMEM_T0, 0);
    cp_commit();

    for (int ch = 0; ch < NCH; ch++) {
        if (ch + 1 < NCH) {
            fill(SMEM_T0 + (uint32_t)(((ch + 1) & 1) * BUF_BYTES), (ch + 1) * KC);
            cp_commit();
            cp_wait1();
        } else {
            cp_wait0();
        }
        __syncthreads();

        const uint32_t tAhi = SMEM_T0 + (uint32_t)((ch & 1) * BUF_BYTES);
        const uint32_t tAlo = tAhi + TILE_BYTES;
        const uint32_t tBhi = tAlo + TILE_BYTES;
        const uint32_t tBlo = tBhi + TILE_BYTES;

        #pragma unroll
        for (int ks = 0; ks < KC; ks += 16) {
            uint32_t aHi[4][4], aLo[4][4];
            #pragma unroll
            for (int mt = 0; mt < 4; mt++) {
                uint32_t off = (uint32_t)(aOff[mt] + ks) * 2;
                ldsm4(aHi[mt][0], aHi[mt][1], aHi[mt][2], aHi[mt][3], tAhi + off);
                ldsm4(aLo[mt][0], aLo[mt][1], aLo[mt][2], aLo[mt][3], tAlo + off);
            }
            #pragma unroll
            for (int nt = 0; nt < 4; nt++) {
                uint32_t off = (uint32_t)(bOff[nt] + ks) * 2;
                uint32_t bh0, bh1, bl0, bl1;
                ldsm2(bh0, bh1, tBhi + off);
                ldsm2(bl0, bl1, tBlo + off);
                #pragma unroll
                for (int mt = 0; mt < 4; mt++) {
                    float* c = acc[mt][nt];
                    mma_bf16(c[0], c[1], c[2], c[3],
                             aHi[mt][0], aHi[mt][1], aHi[mt][2], aHi[mt][3], bh0, bh1);
                }
                #pragma unroll
                for (int mt = 0; mt < 4; mt++) {
                    float* c = acc[mt][nt];
                    mma_bf16(c[0], c[1], c[2], c[3],
                             aHi[mt][0], aHi[mt][1], aHi[mt][2], aHi[mt][3], bl0, bl1);
                }
                #pragma unroll
                for (int mt = 0; mt < 4; mt++) {
                    float* c = acc[mt][nt];
                    mma_bf16(c[0], c[1], c[2], c[3],
                             aLo[mt][0], aLo[mt][1], aLo[mt][2], aLo[mt][3], bh0, bh1);
                }
            }
        }
        __syncthreads();
    }

    // Epilogue: S = d2 - 2*dot, float2 per fragment row pair.
    #pragma unroll
    for (int mt = 0; mt < 4; mt++) {
        int q0 = bm + wm * 64 + mt * 16 + g;
        #pragma unroll
        for (int nt = 0; nt < 4; nt++) {
            int lc = wn * 32 + nt * 8 + tg * 2;
            int n = bn + lc;
            if (n < N) {
                float d0 = Ds[lc], d1 = Ds[lc + 1];
                float* c = acc[mt][nt];
                float2 v0 = make_float2(d0 - 2.f * c[0], d1 - 2.f * c[1]);
                *(float2*)(g_S + (size_t)q0 * N + n) = v0;
                float2 v1 = make_float2(d0 - 2.f * c[2], d1 - 2.f * c[3]);
                *(float2*)(g_S + (size_t)(q0 + 8) * N + n) = v1;
            }
        }
    }
}

// ---------------------------------------------------------------------------
// Kernel 3: per-query top-10 + mode. float4-vectorized streaming scan.
// Global merge tie-breaks (value, index) so per-thread assignment order
// does not affect the selected set; matches jax top_k + argmax-mode.
// ---------------------------------------------------------------------------
__device__ __forceinline__ int load_label(const void* targets, int idx, int lab32) {
    if (lab32) return ((const int*)targets)[idx];
    return (int)((const long long*)targets)[idx];
}

__global__ void topk_mode_kernel(const void* __restrict__ targets,
                                 float* __restrict__ out, int N) {
    const int q = blockIdx.x;
    const float* row = g_S + (size_t)q * N;
    const int t = threadIdx.x;
    const float INF = __int_as_float(0x7f800000);

    float bv[10]; int bi[10];
    #pragma unroll
    for (int r = 0; r < 10; r++) { bv[r] = INF; bi[r] = 0x7fffffff; }
    float worst = INF;

    auto insert = [&](float v, int n) {
        if (v < worst) {
            int p = 9;
            while (p > 0 && v < bv[p - 1]) {
                bv[p] = bv[p - 1]; bi[p] = bi[p - 1]; p--;
            }
            bv[p] = v; bi[p] = n;
            worst = bv[9];
        }
    };

    const int N4 = N >> 2;
    const float4* row4 = (const float4*)row;
    for (int n4 = t; n4 < N4; n4 += 256) {
        float4 v = row4[n4];
        int n = n4 * 4;
        insert(v.x, n);
        insert(v.y, n + 1);
        insert(v.z, n + 2);
        insert(v.w, n + 3);
    }
    for (int n = N4 * 4 + t; n < N; n += 256) insert(row[n], n);

    __shared__ float sv[2560];
    __shared__ int   si[2560];
    __shared__ float rv[256];
    __shared__ int   ri[256];
    __shared__ int   rslot[256];

    #pragma unroll
    for (int r = 0; r < 10; r++) { sv[t * 10 + r] = bv[r]; si[t * 10 + r] = bi[r]; }
    __syncthreads();

    __shared__ int s_topidx[10];
    for (int round = 0; round < 10; round++) {
        float mv = INF; int mi = 0x7fffffff; int ms = t * 10;
        #pragma unroll
        for (int r = 0; r < 10; r++) {
            float v = sv[t * 10 + r]; int i = si[t * 10 + r];
            if (v < mv || (v == mv && i < mi)) { mv = v; mi = i; ms = t * 10 + r; }
        }
        rv[t] = mv; ri[t] = mi; rslot[t] = ms;
        __syncthreads();
        if (t == 0) {
            float gv = INF; int gi = 0x7fffffff; int gs = 0;
            for (int u = 0; u < 256; u++) {
                if (rv[u] < gv || (rv[u] == gv && ri[u] < gi)) {
                    gv = rv[u]; gi = ri[u]; gs = rslot[u];
                }
            }
            s_topidx[round] = gi;
            sv[gs] = INF; si[gs] = 0x7fffffff;
        }
        __syncthreads();
    }

    if (t == 0) {
        int lab32 = g_lab32;
        int lab[10];
        for (int r = 0; r < 10; r++) lab[r] = load_label(targets, s_topidx[r], lab32);
        int bestc = -1, bestl = 0x7fffffff;
        for (int r = 0; r < 10; r++) {
            int c = 0;
            for (int s = 0; s < 10; s++) c += (lab[s] == lab[r]);
            int l = lab[r];
            if (c > bestc || (c == bestc && l < bestl)) { bestc = c; bestl = l; }
        }
        out[q] = (float)bestl;
    }
}

// ---------------------------------------------------------------------------
extern "C" void kernel_launch(void* const* d_in, const int* in_sizes, int n_in,
                              void* d_out, int out_size) {
    const float* X    = (const float*)d_in[0];
    const float* data = (const float*)d_in[1];
    const void*  targets = d_in[2];
    float*       out  = (float*)d_out;

    int szX = in_sizes[0], szD = in_sizes[1];
    if (szX > szD) {
        const float* tmp = X; X = data; data = tmp;
        int ts = szX; szX = szD; szD = ts;
    }
    int N = in_sizes[2];     // 50000
    int Q = szX / KDIM;      // 1024

    const int smem_bytes = 512 + 2 * BUF_BYTES;   // 82432
    cudaFuncSetAttribute(gemm_mma_kernel,
                         cudaFuncAttributeMaxDynamicSharedMemorySize, smem_bytes);

    conv_kernel<<<(N + Q + 7) / 8, 256>>>(data, X, (const unsigned int*)targets, N, Q);

    dim3 g((Q + TILE - 1) / TILE, (N + TILE - 1) / TILE);
    gemm_mma_kernel<<<g, 256, smem_bytes>>>(Q, N);

    topk_mode_kernel<<<Q, 256>>>(targets, out, N);
}